// round 4
// baseline (speedup 1.0000x reference)
#include <cuda_runtime.h>
#include <cuda_bf16.h>
#include <cuda_fp16.h>
#include <cstdint>
#include <cstddef>

// ============================================================
// QuantizedLinear: y[M,N] = (x[M,K] . Wq[N,K]^T) * scale[N]
//                           - scale[N]*zp[N]*rowsum(x)[M] + bias[N]
//
// Base-PTX path (harness PTX target is sm_103, no 'a' features):
//   x -> per-row 16-bit quantization, split into two int8 digits.
//   Two exact int8 IMMA GEMMs (mma.sync.m16n8k32.s8) into int32 accums.
//   y_int = 256*acc_hi + acc_lo (exact), scaled in fp32 epilogue.
//
// R3: the weight buffer's on-wire dtype is unknown (harness may widen
// int8 -> int32/float32/bf16/f16). A device-side detector classifies the
// raw bit patterns and a converter canonicalizes to int8 scratch.
// ============================================================

constexpr int DIM_M = 8192;   // B*S
constexpr int DIM_K = 4096;   // IN
constexpr int DIM_N = 16384;  // OUT

constexpr int BM = 128;
constexpr int BN = 128;
constexpr int BK = 128;                  // int8 elements per K-chunk (=128B rows)
constexpr int NITER = DIM_K / BK;        // 32
constexpr int A_BYTES = BM * BK;         // 16384 per digit
constexpr int B_BYTES = BN * BK;         // 16384
constexpr int BUF_BYTES = 2 * A_BYTES + B_BYTES;   // 48KB
constexpr int SMEM_BYTES = 2 * BUF_BYTES;          // 96KB

// weight formats
constexpr int FMT_I8 = 0, FMT_I32 = 1, FMT_F32 = 2, FMT_BF16 = 3, FMT_F16 = 4;

// ---- device scratch (static __device__ globals: allowed) ----
__device__ __align__(128) int8_t g_xhi[(size_t)DIM_M * DIM_K];
__device__ __align__(128) int8_t g_xlo[(size_t)DIM_M * DIM_K];
__device__ __align__(128) int8_t g_w8 [(size_t)DIM_N * DIM_K];
__device__ float g_s16[DIM_M];
__device__ float g_rowsum[DIM_M];
__device__ int   g_wfmt;

// ============================================================
// helpers (base PTX only)
// ============================================================
__device__ __forceinline__ uint32_t smem_u32(const void* p) {
    uint32_t a;
    asm("{ .reg .u64 t; cvta.to.shared.u64 t, %1; cvt.u32.u64 %0, t; }" : "=r"(a) : "l"(p));
    return a;
}

__device__ __forceinline__ void cp_async16(uint32_t saddr, const void* gptr) {
    asm volatile("cp.async.cg.shared.global [%0], [%1], 16;" :: "r"(saddr), "l"(gptr));
}
#define CP_COMMIT() asm volatile("cp.async.commit_group;" ::: "memory")
#define CP_WAIT(N)  asm volatile("cp.async.wait_group %0;" :: "n"(N) : "memory")

__device__ __forceinline__ void ldsm_x4(uint32_t (&r)[4], uint32_t addr) {
    asm volatile("ldmatrix.sync.aligned.m8n8.x4.shared.b16 {%0,%1,%2,%3}, [%4];"
                 : "=r"(r[0]), "=r"(r[1]), "=r"(r[2]), "=r"(r[3]) : "r"(addr));
}

__device__ __forceinline__ void mma_s8(int (&c)[4], const uint32_t (&a)[4],
                                       uint32_t b0, uint32_t b1) {
    asm volatile(
        "mma.sync.aligned.m16n8k32.row.col.s32.s8.s8.s32 "
        "{%0,%1,%2,%3}, {%4,%5,%6,%7}, {%8,%9}, {%0,%1,%2,%3};"
        : "+r"(c[0]), "+r"(c[1]), "+r"(c[2]), "+r"(c[3])
        : "r"(a[0]), "r"(a[1]), "r"(a[2]), "r"(a[3]), "r"(b0), "r"(b1));
}

// SW128-style swizzle on 128B rows: chunk c (16B) of row r -> c ^ (r&7)
__device__ __forceinline__ uint32_t swz(uint32_t row, uint32_t cbyte) {
    return row * 128u + (cbyte ^ ((row & 7u) << 4));
}

// ============================================================
// Weight dtype detection + canonicalization to int8
// ============================================================
__device__ __forceinline__ int f32_smallint(float v) {
    return isfinite(v) && fabsf(v) <= 128.f && v == truncf(v);
}

__global__ void detect_w_kernel(const uint32_t* __restrict__ w) {
    const int tid = threadIdx.x;
    int ok_i32 = 1, ok_f32 = 1, ok_bf16 = 1, ok_f16 = 1;
    #pragma unroll
    for (int j = 0; j < 4; ++j) {
        uint32_t u = w[tid + j * 256];
        int iv = (int)u;
        ok_i32 &= (iv >= -128 && iv <= 127);
        ok_f32 &= f32_smallint(__int_as_float(u));
        float b0 = __int_as_float((u & 0xFFFFu) << 16);
        float b1 = __int_as_float(u & 0xFFFF0000u);
        ok_bf16 &= f32_smallint(b0) & f32_smallint(b1);
        __half_raw h0r; h0r.x = (unsigned short)(u & 0xFFFFu);
        __half_raw h1r; h1r.x = (unsigned short)(u >> 16);
        ok_f16 &= f32_smallint(__half2float(__half(h0r))) &
                  f32_smallint(__half2float(__half(h1r)));
    }
    ok_i32  = __syncthreads_and(ok_i32);
    ok_f32  = __syncthreads_and(ok_f32);
    ok_bf16 = __syncthreads_and(ok_bf16);
    ok_f16  = __syncthreads_and(ok_f16);
    if (tid == 0) {
        int f = FMT_I8;
        if (ok_i32) f = FMT_I32;
        else if (ok_f32) f = FMT_F32;
        else if (ok_bf16) f = FMT_BF16;
        else if (ok_f16) f = FMT_F16;
        g_wfmt = f;
    }
}

__global__ void __launch_bounds__(256) convert_w_kernel(const void* __restrict__ wraw) {
    const int f = g_wfmt;
    const size_t n4 = (size_t)DIM_N * DIM_K / 4;   // groups of 4 elements
    char4* dst = (char4*)g_w8;
    const size_t stride = (size_t)gridDim.x * blockDim.x;
    size_t i = (size_t)blockIdx.x * blockDim.x + threadIdx.x;
    if (f == FMT_I8) {
        const uint32_t* src = (const uint32_t*)wraw;
        for (; i < n4; i += stride) ((uint32_t*)dst)[i] = src[i];
    } else if (f == FMT_I32) {
        const int4* src = (const int4*)wraw;
        for (; i < n4; i += stride) {
            int4 v = src[i];
            dst[i] = make_char4((char)v.x, (char)v.y, (char)v.z, (char)v.w);
        }
    } else if (f == FMT_F32) {
        const float4* src = (const float4*)wraw;
        for (; i < n4; i += stride) {
            float4 v = src[i];
            dst[i] = make_char4((char)__float2int_rn(v.x), (char)__float2int_rn(v.y),
                                (char)__float2int_rn(v.z), (char)__float2int_rn(v.w));
        }
    } else if (f == FMT_BF16) {
        const uint2* src = (const uint2*)wraw;
        for (; i < n4; i += stride) {
            uint2 v = src[i];
            float a = __int_as_float((v.x & 0xFFFFu) << 16);
            float b = __int_as_float(v.x & 0xFFFF0000u);
            float c = __int_as_float((v.y & 0xFFFFu) << 16);
            float d = __int_as_float(v.y & 0xFFFF0000u);
            dst[i] = make_char4((char)__float2int_rn(a), (char)__float2int_rn(b),
                                (char)__float2int_rn(c), (char)__float2int_rn(d));
        }
    } else {  // FMT_F16
        const uint2* src = (const uint2*)wraw;
        for (; i < n4; i += stride) {
            uint2 v = src[i];
            __half_raw r0; r0.x = (unsigned short)(v.x & 0xFFFFu);
            __half_raw r1; r1.x = (unsigned short)(v.x >> 16);
            __half_raw r2; r2.x = (unsigned short)(v.y & 0xFFFFu);
            __half_raw r3; r3.x = (unsigned short)(v.y >> 16);
            dst[i] = make_char4((char)__float2int_rn(__half2float(__half(r0))),
                                (char)__float2int_rn(__half2float(__half(r1))),
                                (char)__float2int_rn(__half2float(__half(r2))),
                                (char)__float2int_rn(__half2float(__half(r3))));
        }
    }
}

// ============================================================
// Prep: per-row 16-bit quantization of x into two int8 digits,
// plus row sums (zero-point term) and per-row step.
// ============================================================
__global__ void __launch_bounds__(256) quant_x_kernel(const float* __restrict__ x) {
    __shared__ float4 srow[DIM_K / 4];   // 16KB
    __shared__ float red_mx[8], red_sm[8];
    const int m = blockIdx.x;
    const int tid = threadIdx.x;
    const float4* xr = (const float4*)(x + (size_t)m * DIM_K);

    float mx = 0.f, sm = 0.f;
    #pragma unroll
    for (int j = 0; j < 4; ++j) {
        float4 v = xr[tid + j * 256];
        srow[tid + j * 256] = v;
        mx = fmaxf(mx, fmaxf(fmaxf(fabsf(v.x), fabsf(v.y)), fmaxf(fabsf(v.z), fabsf(v.w))));
        sm += v.x + v.y + v.z + v.w;
    }
    #pragma unroll
    for (int o = 16; o; o >>= 1) {
        mx = fmaxf(mx, __shfl_xor_sync(0xFFFFFFFFu, mx, o));
        sm += __shfl_xor_sync(0xFFFFFFFFu, sm, o);
    }
    if ((tid & 31) == 0) { red_mx[tid >> 5] = mx; red_sm[tid >> 5] = sm; }
    __syncthreads();
    if (tid == 0) {
        float tmx = 0.f, tsm = 0.f;
        #pragma unroll
        for (int w = 0; w < 8; ++w) { tmx = fmaxf(tmx, red_mx[w]); tsm += red_sm[w]; }
        red_mx[0] = tmx; red_sm[0] = tsm;
    }
    __syncthreads();
    mx = red_mx[0];
    const float safe = fmaxf(mx, 1e-30f);
    const float inv = 32639.f / safe;          // 32639 = 256*127+127
    char4* hi = (char4*)(g_xhi + (size_t)m * DIM_K);
    char4* lo = (char4*)(g_xlo + (size_t)m * DIM_K);
    #pragma unroll
    for (int j = 0; j < 4; ++j) {
        float4 v = srow[tid + j * 256];
        int q0 = __float2int_rn(v.x * inv);
        int q1 = __float2int_rn(v.y * inv);
        int q2 = __float2int_rn(v.z * inv);
        int q3 = __float2int_rn(v.w * inv);
        int l0 = ((q0 + 128) & 255) - 128, h0 = (q0 - l0) >> 8;
        int l1 = ((q1 + 128) & 255) - 128, h1 = (q1 - l1) >> 8;
        int l2 = ((q2 + 128) & 255) - 128, h2 = (q2 - l2) >> 8;
        int l3 = ((q3 + 128) & 255) - 128, h3 = (q3 - l3) >> 8;
        hi[tid + j * 256] = make_char4((char)h0, (char)h1, (char)h2, (char)h3);
        lo[tid + j * 256] = make_char4((char)l0, (char)l1, (char)l2, (char)l3);
    }
    if (tid == 0) { g_s16[m] = safe / 32639.f; g_rowsum[m] = red_sm[0]; }
}

// ============================================================
// Main GEMM: 128x128x128 tile, 8 warps (64x32 warp tile),
// double-buffered cp.async, two-digit IMMA, fused fp32 epilogue.
// ============================================================
__global__ void __launch_bounds__(256, 1) qlin_gemm(
    float* __restrict__ out,
    const float* __restrict__ scale,
    const float* __restrict__ zp,
    const float* __restrict__ bias)
{
    extern __shared__ __align__(1024) char smem[];
    const uint32_t sbase = smem_u32(smem);

    const int tid = threadIdx.x;
    const int wid = tid >> 5;
    const int lane = tid & 31;

    // band raster: 8 m-tiles x 16 n-tiles per band block (L2 reuse)
    const int bid = blockIdx.x;
    const int blk = bid >> 7;
    const int within = bid & 127;
    const int mt = (blk & 7) * 8 + (within & 7);
    const int nt = (blk >> 3) * 16 + (within >> 3);
    const int m0 = mt * BM;
    const int n0 = nt * BN;

    const int wm = wid & 1;       // 2 warps along M
    const int wn = wid >> 1;      // 4 warps along N
    const int wrow0 = wm * 64;
    const int wcol0 = wn * 32;

    const int8_t* aHiBase = g_xhi + (size_t)m0 * DIM_K;
    const int8_t* aLoBase = g_xlo + (size_t)m0 * DIM_K;
    const int8_t* bBase   = g_w8  + (size_t)n0 * DIM_K;

    const int ldrow = tid >> 3;          // 0..31
    const int ldseg = tid & 7;           // 16B segment within 128B row

    auto issue_load = [&](int it, int buf) {
        const uint32_t bb = sbase + (uint32_t)buf * BUF_BYTES;
        const int k0 = it * BK;
        #pragma unroll
        for (int j = 0; j < 4; ++j) {
            const int row = ldrow + j * 32;
            const uint32_t so = swz((uint32_t)row, (uint32_t)(ldseg * 16));
            cp_async16(bb + so,               aHiBase + (size_t)row * DIM_K + k0 + ldseg * 16);
            cp_async16(bb + A_BYTES + so,     aLoBase + (size_t)row * DIM_K + k0 + ldseg * 16);
            cp_async16(bb + 2 * A_BYTES + so, bBase   + (size_t)row * DIM_K + k0 + ldseg * 16);
        }
        CP_COMMIT();
    };

    // ldmatrix lane->address maps (swizzle folded; ^ (ks<<5) steps K)
    const uint32_t rA = (uint32_t)(lane & 15);
    const uint32_t cA = (lane & 16) ? 16u : 0u;
    const uint32_t rB = (uint32_t)((lane & 7) + ((lane & 16) ? 8 : 0));
    const uint32_t cB = (lane & 8) ? 16u : 0u;

    int ch[4][4][4];   // acc hi digit
    int cl[4][4][4];   // acc lo digit
    #pragma unroll
    for (int i = 0; i < 4; ++i)
        #pragma unroll
        for (int j = 0; j < 4; ++j)
            #pragma unroll
            for (int k = 0; k < 4; ++k) { ch[i][j][k] = 0; cl[i][j][k] = 0; }

    issue_load(0, 0);

    for (int it = 0; it < NITER; ++it) {
        if (it + 1 < NITER) issue_load(it + 1, (it + 1) & 1);
        if (it + 1 < NITER) { CP_WAIT(1); } else { CP_WAIT(0); }
        __syncthreads();

        const uint32_t bb = sbase + (uint32_t)(it & 1) * BUF_BYTES;
        uint32_t aHi0[4], aLo0[4];
        #pragma unroll
        for (int mi = 0; mi < 4; ++mi) {
            const uint32_t row = (uint32_t)(wrow0 + mi * 16) + rA;
            const uint32_t off = swz(row, cA);
            aHi0[mi] = bb + off;
            aLo0[mi] = bb + A_BYTES + off;
        }
        uint32_t b0g[2];
        #pragma unroll
        for (int g = 0; g < 2; ++g) {
            const uint32_t row = (uint32_t)(wcol0 + g * 16) + rB;
            b0g[g] = bb + 2 * A_BYTES + swz(row, cB);
        }

        #pragma unroll
        for (int ks = 0; ks < 4; ++ks) {
            const uint32_t kx = (uint32_t)(ks << 5);
            uint32_t ahi[4][4], alo[4][4], bf[2][4];
            #pragma unroll
            for (int mi = 0; mi < 4; ++mi) {
                ldsm_x4(ahi[mi], aHi0[mi] ^ kx);
                ldsm_x4(alo[mi], aLo0[mi] ^ kx);
            }
            #pragma unroll
            for (int g = 0; g < 2; ++g) ldsm_x4(bf[g], b0g[g] ^ kx);

            #pragma unroll
            for (int mi = 0; mi < 4; ++mi) {
                #pragma unroll
                for (int ni = 0; ni < 4; ++ni) {
                    const int g = ni >> 1;
                    const int s = (ni & 1) * 2;
                    mma_s8(ch[mi][ni], ahi[mi], bf[g][s], bf[g][s + 1]);
                    mma_s8(cl[mi][ni], alo[mi], bf[g][s], bf[g][s + 1]);
                }
            }
        }
        __syncthreads();
    }

    // ---- epilogue: y = scale*s16*(256*hi+lo) - scale*zp*rowsum + bias ----
    const int col_in = (lane & 3) * 2;
    const int row_in = lane >> 2;
    #pragma unroll
    for (int mi = 0; mi < 4; ++mi) {
        const int r0 = m0 + wrow0 + mi * 16 + row_in;
        const int r1 = r0 + 8;
        const float s0 = g_s16[r0], rs0 = g_rowsum[r0];
        const float s1 = g_s16[r1], rs1 = g_rowsum[r1];
        #pragma unroll
        for (int ni = 0; ni < 4; ++ni) {
            const int c = n0 + wcol0 + ni * 8 + col_in;
            const float scA = __ldg(scale + c),     scB = __ldg(scale + c + 1);
            const float zA  = __ldg(zp + c),        zB  = __ldg(zp + c + 1);
            const float bA  = __ldg(bias + c),      bB_ = __ldg(bias + c + 1);
            const int* H = ch[mi][ni];
            const int* L = cl[mi][ni];
            float y00 = fmaf(256.f, (float)H[0], (float)L[0]) * s0;
            float y01 = fmaf(256.f, (float)H[1], (float)L[1]) * s0;
            float y10 = fmaf(256.f, (float)H[2], (float)L[2]) * s1;
            float y11 = fmaf(256.f, (float)H[3], (float)L[3]) * s1;
            float2 v0, v1;
            v0.x = fmaf(scA, y00, fmaf(-scA * zA, rs0, bA));
            v0.y = fmaf(scB, y01, fmaf(-scB * zB, rs0, bB_));
            v1.x = fmaf(scA, y10, fmaf(-scA * zA, rs1, bA));
            v1.y = fmaf(scB, y11, fmaf(-scB * zB, rs1, bB_));
            *(float2*)(out + (size_t)r0 * DIM_N + c) = v0;
            *(float2*)(out + (size_t)r1 * DIM_N + c) = v1;
        }
    }
}

// ============================================================
// Host launch
// ============================================================
extern "C" void kernel_launch(void* const* d_in, const int* in_sizes, int n_in,
                              void* d_out, int out_size) {
    const float* x    = (const float*)d_in[0];
    const void*  wraw = d_in[1];                 // dtype detected on device
    const float* wsc  = (const float*)d_in[2];
    const float* wzp  = (const float*)d_in[3];
    const float* bias = (const float*)d_in[4];
    float* out = (float*)d_out;

    cudaFuncSetAttribute(qlin_gemm, cudaFuncAttributeMaxDynamicSharedMemorySize, SMEM_BYTES);

    detect_w_kernel<<<1, 256>>>((const uint32_t*)wraw);
    convert_w_kernel<<<2048, 256>>>(wraw);
    quant_x_kernel<<<DIM_M, 256>>>(x);
    qlin_gemm<<<(DIM_M / BM) * (DIM_N / BN), 256, SMEM_BYTES>>>(out, wsc, wzp, bias);
}